// round 7
// baseline (speedup 1.0000x reference)
#include <cuda_runtime.h>
#include <cstdint>
#include <math.h>

#define WW 512
#define HH 512
#define NB 8
#define NK 8
#define NC 3
#define HW (512 * 512)   /* 262144 */
#define CHW (NC * HW)    /* 786432 */

// output region offsets (float elements), tuple order:
// best_warped[B,C,H,W], best_idx[B], best_mse[B], all_warped_b[B,K,C,H,W], all_mse[B,K], flows[K,H,W,2]
#define OFF_BW   0ull
#define OFF_IDX  6291456ull
#define OFF_BMSE 6291464ull
#define OFF_AW   6291472ull
#define OFF_AMSE 56623120ull
#define OFF_FL   56623184ull

// scratch (device globals -- no allocation allowed)
__device__ float g_sx[NK * HH];          // dx[k][y]  (x-shift, row-constant)
__device__ float g_sy[NK * WW];          // dy[k][x]  (y-shift, col-varying)
__device__ float g_part[NB * NK * HH];   // per-row partial SSE
__device__ int   g_best[NB];

__device__ __forceinline__ float softplusf(float x) {
    return fmaxf(x, 0.f) + log1pf(expf(-fabsf(x)));
}

// ---------------- shift tables ----------------
__global__ void k_tables(const float* __restrict__ cp) {
    int k = blockIdx.x, t = threadIdx.x;  // t in [0,512)
    float p0 = cp[k * 4 + 0], p1 = cp[k * 4 + 1];
    float p2 = cp[k * 4 + 2], p3 = cp[k * 4 + 3];
    float v_left = 0.5f * tanhf(p0);
    float u_top  = 0.5f * tanhf(p1);
    float decay_x = softplusf(p2);
    float decay_y = softplusf(p3);
    float tc = (float)t * (1.0f / 511.0f);
    g_sx[k * HH + t] = u_top  * expf(-decay_y * tc);  // dx(k, y=t)
    g_sy[k * WW + t] = v_left * expf(-decay_x * tc);  // dy(k, x=t)
}

// Load 3-row x 6-col (clamped halo) register neighborhood for all channels.
__device__ __forceinline__ void load_nb(const float* __restrict__ pred, int b,
                                        int y, int x0, float (&nb)[NC][3][6]) {
    const int ym1 = (y > 0) ? y - 1 : 0;
    const int yp1 = (y < HH - 1) ? y + 1 : HH - 1;
    const int xl = (x0 > 0) ? x0 - 1 : 0;
    const int xr = (x0 + 4 < WW) ? x0 + 4 : WW - 1;
    const int rows[3] = {ym1, y, yp1};
#pragma unroll
    for (int c = 0; c < NC; c++) {
#pragma unroll
        for (int r = 0; r < 3; r++) {
            const float* pr = pred + ((size_t)(b * NC + c) * HH + rows[r]) * WW;
            nb[c][r][0] = __ldg(pr + xl);
            float4 v = *reinterpret_cast<const float4*>(pr + x0);
            nb[c][r][1] = v.x; nb[c][r][2] = v.y;
            nb[c][r][3] = v.z; nb[c][r][4] = v.w;
            nb[c][r][5] = __ldg(pr + xr);
        }
    }
}

// Shared weight derivation: wx, wy[4], tap bases.
struct Taps { float wx; float wy[4]; bool xneg; bool yneg; };
__device__ __forceinline__ Taps make_taps(float dxk, const float (&dys)[4]) {
    Taps tp;
    tp.wx = dxk - floorf(dxk);
    tp.xneg = dxk < 0.f;
    tp.yneg = dys[0] < 0.f;                 // sign uniform along x (exp > 0)
    float of = tp.yneg ? -1.f : 0.f;
#pragma unroll
    for (int j = 0; j < 4; j++) tp.wy[j] = dys[j] - of;
    return tp;
}

// ---------------- phase-1 body: MSE only, no stores ----------------
template <int CB, int RB>
__device__ __forceinline__ float mse_body(const float (&nb)[NC][3][6],
                                          const float (&gv)[NC][4],
                                          float wx, const float (&wy)[4]) {
    float a = 0.f;
#pragma unroll
    for (int c = 0; c < NC; c++) {
#pragma unroll
        for (int j = 0; j < 4; j++) {
            float p00 = nb[c][RB][CB + j],     p01 = nb[c][RB][CB + j + 1];
            float p10 = nb[c][RB + 1][CB + j], p11 = nb[c][RB + 1][CB + j + 1];
            float s0 = fmaf(wx, p01 - p00, p00);
            float s1 = fmaf(wx, p11 - p10, p10);
            float v  = fmaf(wy[j], s1 - s0, s0);
            float d = v - gv[c][j];
            a = fmaf(d, d, a);
        }
    }
    return a;
}

// ---------------- phase-2 body: stores (all_warped + optional best_warped) ----------------
template <int CB, int RB>
__device__ __forceinline__ void store_body(const float (&nb)[NC][3][6],
                                           float wx, const float (&wy)[4],
                                           float* ob, float* ob_best,
                                           bool is_best) {
#pragma unroll
    for (int c = 0; c < NC; c++) {
        float ov[4];
#pragma unroll
        for (int j = 0; j < 4; j++) {
            float p00 = nb[c][RB][CB + j],     p01 = nb[c][RB][CB + j + 1];
            float p10 = nb[c][RB + 1][CB + j], p11 = nb[c][RB + 1][CB + j + 1];
            float s0 = fmaf(wx, p01 - p00, p00);
            float s1 = fmaf(wx, p11 - p10, p10);
            ov[j] = fmaf(wy[j], s1 - s0, s0);
        }
        float4 v4 = make_float4(ov[0], ov[1], ov[2], ov[3]);
        __stcs(reinterpret_cast<float4*>(ob + (size_t)c * HW), v4);
        if (is_best)
            __stcs(reinterpret_cast<float4*>(ob_best + (size_t)c * HW), v4);
    }
}

// ---------------- phase 1: MSE only (reads pred+gt, no big stores) ----------------
__global__ __launch_bounds__(128) void k_mse(const float* __restrict__ pred,
                                             const float* __restrict__ gt,
                                             float* __restrict__ out) {
    const int y = blockIdx.x;
    const int b = blockIdx.y;
    const int t = threadIdx.x;
    const int x0 = t * 4;

    float nb[NC][3][6];
    load_nb(pred, b, y, x0, nb);

    float gv[NC][4];
#pragma unroll
    for (int c = 0; c < NC; c++) {
        float4 g4 = __ldcs(reinterpret_cast<const float4*>(
            gt + ((size_t)(b * NC + c) * HH + y) * WW + x0));  // read-once
        gv[c][0] = g4.x; gv[c][1] = g4.y; gv[c][2] = g4.z; gv[c][3] = g4.w;
    }

    float acc[NK];
#pragma unroll
    for (int k = 0; k < NK; k++) {
        float dxk = g_sx[k * HH + y];          // uniform per block
        float4 dy4 = *reinterpret_cast<const float4*>(g_sy + k * WW + x0);
        float dys[4] = {dy4.x, dy4.y, dy4.z, dy4.w};
        Taps tp = make_taps(dxk, dys);
        float a;
        if (tp.xneg) a = tp.yneg ? mse_body<0, 0>(nb, gv, tp.wx, tp.wy)
                                 : mse_body<0, 1>(nb, gv, tp.wx, tp.wy);
        else         a = tp.yneg ? mse_body<1, 0>(nb, gv, tp.wx, tp.wy)
                                 : mse_body<1, 1>(nb, gv, tp.wx, tp.wy);
        acc[k] = a;
    }

    // deterministic block reduction (no atomics)
    __shared__ float sw[NK][4];
    int lane = t & 31, wid = t >> 5;
#pragma unroll
    for (int k = 0; k < NK; k++) {
        float v = acc[k];
        v += __shfl_down_sync(0xffffffffu, v, 16);
        v += __shfl_down_sync(0xffffffffu, v, 8);
        v += __shfl_down_sync(0xffffffffu, v, 4);
        v += __shfl_down_sync(0xffffffffu, v, 2);
        v += __shfl_down_sync(0xffffffffu, v, 1);
        if (lane == 0) sw[k][wid] = v;
    }
    __syncthreads();
    if (t < NK) {
        float s = sw[t][0] + sw[t][1] + sw[t][2] + sw[t][3];
        g_part[((size_t)b * NK + t) * HH + y] = s;
    }
}

// ---------------- fused reduce + argmin: one block per batch ----------------
__global__ void k_finish(float* __restrict__ out) {
    int b = blockIdx.x;
    int t = threadIdx.x;          // 256
    int k = t >> 5, lane = t & 31;
    const float* p = g_part + ((size_t)b * NK + k) * HH;
    float s = 0.f;
#pragma unroll
    for (int i = 0; i < 16; i++) s += p[lane + i * 32];
    s += __shfl_down_sync(0xffffffffu, s, 16);
    s += __shfl_down_sync(0xffffffffu, s, 8);
    s += __shfl_down_sync(0xffffffffu, s, 4);
    s += __shfl_down_sync(0xffffffffu, s, 2);
    s += __shfl_down_sync(0xffffffffu, s, 1);
    __shared__ float sh[NK];
    if (lane == 0) {
        float m = s * (1.0f / (float)CHW);
        sh[k] = m;
        out[OFF_AMSE + b * NK + k] = m;
    }
    __syncthreads();
    if (t == 0) {
        float bm = sh[0];
        int bi = 0;
#pragma unroll
        for (int kk = 1; kk < NK; kk++) {
            float m = sh[kk];
            if (m < bm) { bm = m; bi = kk; }   // first-min tiebreak == argmin
        }
        g_best[b] = bi;
        out[OFF_IDX + b] = (float)bi;
        out[OFF_BMSE + b] = bm;
    }
}

// ---------------- phase 2: all stores; 256 thr = 2 rows per block ----------------
__global__ __launch_bounds__(256) void k_store(const float* __restrict__ pred,
                                               float* __restrict__ out) {
    const int t = threadIdx.x & 127;
    const int y = blockIdx.x * 2 + (threadIdx.x >> 7);
    const int b = blockIdx.y;
    const int x0 = t * 4;

    float nb[NC][3][6];
    load_nb(pred, b, y, x0, nb);   // L2-resident from phase 1

    const int kb = g_best[b];      // uniform per block
    float* outAW = out + OFF_AW + (size_t)b * NK * CHW + (size_t)y * WW + x0;
    float* outBW = out + OFF_BW + (size_t)b * CHW + (size_t)y * WW + x0;
    const bool do_flows = (b == 0);

#pragma unroll
    for (int k = 0; k < NK; k++) {
        float dxk = g_sx[k * HH + y];
        float4 dy4 = *reinterpret_cast<const float4*>(g_sy + k * WW + x0);
        float dys[4] = {dy4.x, dy4.y, dy4.z, dy4.w};

        if (do_flows) {   // flows[k,y,x,{dx,dy}] -- piggyback on b==0 blocks
            float* fo = out + OFF_FL + (((size_t)k * HH + y) * WW + x0) * 2;
            __stcs(reinterpret_cast<float4*>(fo),
                   make_float4(dxk, dys[0], dxk, dys[1]));
            __stcs(reinterpret_cast<float4*>(fo + 4),
                   make_float4(dxk, dys[2], dxk, dys[3]));
        }

        Taps tp = make_taps(dxk, dys);
        float* ob = outAW + (size_t)k * CHW;
        bool isb = (k == kb);
        if (tp.xneg) { if (tp.yneg) store_body<0, 0>(nb, tp.wx, tp.wy, ob, outBW, isb);
                       else         store_body<0, 1>(nb, tp.wx, tp.wy, ob, outBW, isb); }
        else         { if (tp.yneg) store_body<1, 0>(nb, tp.wx, tp.wy, ob, outBW, isb);
                       else         store_body<1, 1>(nb, tp.wx, tp.wy, ob, outBW, isb); }
    }
}

extern "C" void kernel_launch(void* const* d_in, const int* in_sizes, int n_in,
                              void* d_out, int out_size) {
    const float* pred = (const float*)d_in[0];
    const float* gt   = (const float*)d_in[1];
    const float* cp   = (const float*)d_in[2];
    float* out = (float*)d_out;
    (void)in_sizes; (void)n_in; (void)out_size;

    k_tables<<<NK, 512>>>(cp);
    k_mse<<<dim3(HH, NB), 128>>>(pred, gt, out);
    k_finish<<<NB, 256>>>(out);
    k_store<<<dim3(HH / 2, NB), 256>>>(pred, out);
}

// round 9
// speedup vs baseline: 1.2915x; 1.2915x over previous
#include <cuda_runtime.h>
#include <cstdint>
#include <math.h>

#define WW 512
#define HH 512
#define NB 8
#define NK 8
#define NC 3
#define HW (512 * 512)   /* 262144 */
#define CHW (NC * HW)    /* 786432 */

// output region offsets (float elements), tuple order:
// best_warped[B,C,H,W], best_idx[B], best_mse[B], all_warped_b[B,K,C,H,W], all_mse[B,K], flows[K,H,W,2]
#define OFF_BW   0ull
#define OFF_IDX  6291456ull
#define OFF_BMSE 6291464ull
#define OFF_AW   6291472ull
#define OFF_AMSE 56623120ull
#define OFF_FL   56623184ull

// scratch (device globals -- no allocation allowed)
__device__ float g_sx[NK * HH];          // dx[k][y]  (x-shift, row-constant)
__device__ float g_sy[NK * WW];          // dy[k][x]  (y-shift, col-varying)
__device__ float g_part[NB * NK * HH];   // per-row partial SSE
__device__ int   g_best[NB];

__device__ __forceinline__ float softplusf(float x) {
    return fmaxf(x, 0.f) + log1pf(expf(-fabsf(x)));
}

// ---------------- shift tables ----------------
__global__ void k_tables(const float* __restrict__ cp) {
    int k = blockIdx.x, t = threadIdx.x;  // t in [0,512)
    float p0 = cp[k * 4 + 0], p1 = cp[k * 4 + 1];
    float p2 = cp[k * 4 + 2], p3 = cp[k * 4 + 3];
    float v_left = 0.5f * tanhf(p0);
    float u_top  = 0.5f * tanhf(p1);
    float decay_x = softplusf(p2);
    float decay_y = softplusf(p3);
    float tc = (float)t * (1.0f / 511.0f);
    g_sx[k * HH + t] = u_top  * expf(-decay_y * tc);  // dx(k, y=t)
    g_sy[k * WW + t] = v_left * expf(-decay_x * tc);  // dy(k, x=t)
}

// single-channel warp body: 3x6 neighborhood -> 4 outputs + SSE partial
// CB: 0 => taps x-1,x ; 1 => taps x,x+1.  RB: 0 => rows ym1,y ; 1 => rows y,yp1.
template <int CB, int RB>
__device__ __forceinline__ float warp_c(const float (&nb)[3][6],
                                        const float (&gv)[4],
                                        float wx, const float (&wy)[4],
                                        float* __restrict__ ob) {
    float a = 0.f;
    float ov[4];
#pragma unroll
    for (int j = 0; j < 4; j++) {
        float p00 = nb[RB][CB + j],     p01 = nb[RB][CB + j + 1];
        float p10 = nb[RB + 1][CB + j], p11 = nb[RB + 1][CB + j + 1];
        float s0 = fmaf(wx, p01 - p00, p00);
        float s1 = fmaf(wx, p11 - p10, p10);
        float v  = fmaf(wy[j], s1 - s0, s0);
        ov[j] = v;
        float d = v - gv[j];
        a = fmaf(d, d, a);
    }
    __stcs(reinterpret_cast<float4*>(ob),
           make_float4(ov[0], ov[1], ov[2], ov[3]));
    return a;
}

// ---------------- fused main: warp + SSE + flows, channel-outer for low regs ----------------
__global__ __launch_bounds__(128) void k_main(const float* __restrict__ pred,
                                              const float* __restrict__ gt,
                                              float* __restrict__ out) {
    const int y = blockIdx.x;
    const int b = blockIdx.y;
    const int t = threadIdx.x;
    const int x0 = t * 4;

    const int ym1 = (y > 0) ? y - 1 : 0;
    const int yp1 = (y < HH - 1) ? y + 1 : HH - 1;
    const int xl = (x0 > 0) ? x0 - 1 : 0;
    const int xr = (x0 + 4 < WW) ? x0 + 4 : WW - 1;
    const int rows[3] = {ym1, y, yp1};

    float acc[NK];
#pragma unroll
    for (int k = 0; k < NK; k++) acc[k] = 0.f;

    float* outAW = out + OFF_AW + (size_t)b * NK * CHW + (size_t)y * WW + x0;

#pragma unroll
    for (int c = 0; c < NC; c++) {
        // one channel's 3x6 clamped neighborhood (18 live floats)
        float nb[3][6];
#pragma unroll
        for (int r = 0; r < 3; r++) {
            const float* pr = pred + ((size_t)(b * NC + c) * HH + rows[r]) * WW;
            nb[r][0] = __ldg(pr + xl);
            float4 v = *reinterpret_cast<const float4*>(pr + x0);
            nb[r][1] = v.x; nb[r][2] = v.y; nb[r][3] = v.z; nb[r][4] = v.w;
            nb[r][5] = __ldg(pr + xr);
        }
        float gv[4];
        {
            float4 g4 = __ldcs(reinterpret_cast<const float4*>(
                gt + ((size_t)(b * NC + c) * HH + y) * WW + x0));  // read-once
            gv[0] = g4.x; gv[1] = g4.y; gv[2] = g4.z; gv[3] = g4.w;
        }

#pragma unroll
        for (int k = 0; k < NK; k++) {
            float dxk = g_sx[k * HH + y];          // L1-resident, uniform per block
            float4 dy4 = *reinterpret_cast<const float4*>(g_sy + k * WW + x0);
            float dys[4] = {dy4.x, dy4.y, dy4.z, dy4.w};

            if (c == 0 && b == 0) {  // flows[k,y,x,{dx,dy}] once per (k,y,x)
                float* fo = out + OFF_FL + (((size_t)k * HH + y) * WW + x0) * 2;
                __stcs(reinterpret_cast<float4*>(fo),
                       make_float4(dxk, dys[0], dxk, dys[1]));
                __stcs(reinterpret_cast<float4*>(fo + 4),
                       make_float4(dxk, dys[2], dxk, dys[3]));
            }

            float wx = dxk - floorf(dxk);
            bool xneg = dxk < 0.f;
            bool yneg = dys[0] < 0.f;             // sign uniform along x (exp > 0)
            float of = yneg ? -1.f : 0.f;
            float wy[4];
#pragma unroll
            for (int j = 0; j < 4; j++) wy[j] = dys[j] - of;

            float* ob = outAW + (size_t)k * CHW + (size_t)c * HW;
            float a;
            if (xneg) a = yneg ? warp_c<0, 0>(nb, gv, wx, wy, ob)
                               : warp_c<0, 1>(nb, gv, wx, wy, ob);
            else      a = yneg ? warp_c<1, 0>(nb, gv, wx, wy, ob)
                               : warp_c<1, 1>(nb, gv, wx, wy, ob);
            acc[k] += a;
        }
    }

    // deterministic block reduction (no atomics)
    __shared__ float sw[NK][4];
    int lane = t & 31, wid = t >> 5;
#pragma unroll
    for (int k = 0; k < NK; k++) {
        float v = acc[k];
        v += __shfl_down_sync(0xffffffffu, v, 16);
        v += __shfl_down_sync(0xffffffffu, v, 8);
        v += __shfl_down_sync(0xffffffffu, v, 4);
        v += __shfl_down_sync(0xffffffffu, v, 2);
        v += __shfl_down_sync(0xffffffffu, v, 1);
        if (lane == 0) sw[k][wid] = v;
    }
    __syncthreads();
    if (t < NK) {
        float s = sw[t][0] + sw[t][1] + sw[t][2] + sw[t][3];
        g_part[((size_t)b * NK + t) * HH + y] = s;
    }
}

// ---------------- fused reduce + argmin: one block per batch ----------------
__global__ void k_finish(float* __restrict__ out) {
    int b = blockIdx.x;
    int t = threadIdx.x;          // 256
    int k = t >> 5, lane = t & 31;
    const float* p = g_part + ((size_t)b * NK + k) * HH;
    float s = 0.f;
#pragma unroll
    for (int i = 0; i < 16; i++) s += p[lane + i * 32];
    s += __shfl_down_sync(0xffffffffu, s, 16);
    s += __shfl_down_sync(0xffffffffu, s, 8);
    s += __shfl_down_sync(0xffffffffu, s, 4);
    s += __shfl_down_sync(0xffffffffu, s, 2);
    s += __shfl_down_sync(0xffffffffu, s, 1);
    __shared__ float sh[NK];
    if (lane == 0) {
        float m = s * (1.0f / (float)CHW);
        sh[k] = m;
        out[OFF_AMSE + b * NK + k] = m;
    }
    __syncthreads();
    if (t == 0) {
        float bm = sh[0];
        int bi = 0;
#pragma unroll
        for (int kk = 1; kk < NK; kk++) {
            float m = sh[kk];
            if (m < bm) { bm = m; bi = kk; }   // first-min tiebreak == argmin
        }
        g_best[b] = bi;
        out[OFF_IDX + b] = (float)bi;
        out[OFF_BMSE + b] = bm;
    }
}

// ---------------- gather best_warped: 4 independent float4 per thread ----------------
// Each block covers 1024 consecutive float4 of one batch (192 blocks per batch).
__global__ __launch_bounds__(256) void k_copy(float* __restrict__ out) {
    const int blocks_per_b = (CHW / 4) / 1024;   // 192
    const int b = blockIdx.x / blocks_per_b;
    const size_t base = (size_t)(blockIdx.x % blocks_per_b) * 1024;
    const int k = g_best[b];                     // uniform (L2-broadcast)

    const float4* src = reinterpret_cast<const float4*>(out) + (OFF_AW / 4) +
                        ((size_t)(b * NK + k)) * (CHW / 4) + base;
    float4* dst = reinterpret_cast<float4*>(out) + (size_t)b * (CHW / 4) + base;

    int t = threadIdx.x;
    float4 v0 = __ldcs(src + t);
    float4 v1 = __ldcs(src + t + 256);
    float4 v2 = __ldcs(src + t + 512);
    float4 v3 = __ldcs(src + t + 768);
    __stcs(dst + t, v0);
    __stcs(dst + t + 256, v1);
    __stcs(dst + t + 512, v2);
    __stcs(dst + t + 768, v3);
}

extern "C" void kernel_launch(void* const* d_in, const int* in_sizes, int n_in,
                              void* d_out, int out_size) {
    const float* pred = (const float*)d_in[0];
    const float* gt   = (const float*)d_in[1];
    const float* cp   = (const float*)d_in[2];
    float* out = (float*)d_out;
    (void)in_sizes; (void)n_in; (void)out_size;

    k_tables<<<NK, 512>>>(cp);
    k_main<<<dim3(HH, NB), 128>>>(pred, gt, out);
    k_finish<<<NB, 256>>>(out);
    k_copy<<<NB * ((CHW / 4) / 1024), 256>>>(out);
}